// round 1
// baseline (speedup 1.0000x reference)
#include <cuda_runtime.h>

// ---------------------------------------------------------------------------
// BoltzmannGateSTE: out = x * (|x| >= T), T = k-th largest |x|, k = int(N/e).
// Exact radix-select on float bit patterns (abs bits order == float order),
// with a sampling-based pivot window so the full-data pass does no per-element
// atomics. Two full-data touches total (read+write in k_main).
// ---------------------------------------------------------------------------

#define HIST1_BINS 8192
#define HIST2_BINS 2048
#define CAND_CAP   (4u * 1024u * 1024u)

__device__ unsigned int g_hist1[HIST1_BINS];
__device__ unsigned int g_hist2[HIST2_BINS];
__device__ unsigned int g_cand_v[CAND_CAP];    // abs bit patterns of candidates
__device__ unsigned int g_cand_idx[CAND_CAP];  // element indices of candidates
__device__ unsigned int g_ncand;
__device__ unsigned int g_cnt_hi;              // #elements with absbits >= pivot_hi
__device__ unsigned int g_pivot_lo;
__device__ unsigned int g_pivot_hi;
__device__ unsigned int g_P;                   // resolved high bits of (v - pivot_lo)
__device__ int          g_m;                   // remaining unresolved bits
__device__ unsigned int g_rr;                  // remaining rank within current window
__device__ int          g_round;
__device__ int          g_done;
__device__ unsigned int g_thr;                 // final threshold bit pattern

// ---------------------------------------------------------------------------
__global__ void k_reset() {
    int t = threadIdx.x;
    for (int i = t; i < HIST1_BINS; i += 1024) g_hist1[i] = 0u;
    for (int i = t; i < HIST2_BINS; i += 1024) g_hist2[i] = 0u;
    if (t == 0) {
        g_ncand = 0u; g_cnt_hi = 0u;
        g_P = 0u; g_m = 0; g_rr = 0u; g_round = 0; g_done = 0; g_thr = 0u;
    }
}

// ---------------------------------------------------------------------------
// Coarse histogram over every 64th element (top 13 bits of abs pattern).
__global__ void k_sample(const float* __restrict__ x, int nsamp) {
    int i = blockIdx.x * blockDim.x + threadIdx.x;
    if (i < nsamp) {
        unsigned int a = __float_as_uint(x[(long long)i << 6]) & 0x7FFFFFFFu;
        atomicAdd(&g_hist1[a >> 18], 1u);
    }
}

// ---------------------------------------------------------------------------
// Find bucket window [b_lo, b_hi] bracketing the threshold from the sample
// histogram (descending rank scan), with big margins. Sets pivots + state.
__global__ void k_scan1(long long k, int nsamp) {
    __shared__ unsigned int cs[1024];
    __shared__ int sh_bhi, sh_blo;
    int t = threadIdx.x;

    unsigned int loc[8];
    unsigned int s = 0u;
#pragma unroll
    for (int j = 0; j < 8; j++) {
        int bin = HIST1_BINS - 1 - (t * 8 + j);   // descending value order
        loc[j] = g_hist1[bin];
        s += loc[j];
    }
    cs[t] = s;
    __syncthreads();
    for (int off = 1; off < 1024; off <<= 1) {
        unsigned int add = (t >= off) ? cs[t - off] : 0u;
        __syncthreads();
        cs[t] += add;
        __syncthreads();
    }
    long long incl = (long long)cs[t];
    long long excl = incl - (long long)s;
    long long tot  = (long long)cs[1023];

    long long sk = k >> 6;                 // expected sample rank of threshold
    if (sk < 1) sk = 1;
    const long long M = 8192;              // ~23 sigma margin
    long long R1 = sk - M; if (R1 < 1) R1 = 1;
    long long R2 = sk + M; if (R2 > tot) R2 = tot;

    if (t == 0) { sh_bhi = HIST1_BINS - 1; sh_blo = 0; }
    __syncthreads();

    if (tot > 0 && excl < R1 && R1 <= incl) {
        long long acc = excl;
#pragma unroll
        for (int j = 0; j < 8; j++) {
            acc += (long long)loc[j];
            if (acc >= R1) { sh_bhi = HIST1_BINS - 1 - (t * 8 + j); break; }
        }
    }
    if (tot > 0 && excl < R2 && R2 <= incl) {
        long long acc = excl;
#pragma unroll
        for (int j = 0; j < 8; j++) {
            acc += (long long)loc[j];
            if (acc >= R2) { sh_blo = HIST1_BINS - 1 - (t * 8 + j); break; }
        }
    }
    __syncthreads();

    if (t == 0) {
        unsigned int plo, phi;
        if (nsamp < 4096 || tot == 0) {
            // tiny-input fallback: full range (only valid when n <= CAND_CAP)
            plo = 0u; phi = 0x80000000u;
        } else {
            int bhi = sh_bhi + 1; if (bhi > HIST1_BINS - 1) bhi = HIST1_BINS - 1;
            int blo = sh_blo - 1; if (blo < 0) blo = 0;
            phi = ((unsigned int)(bhi + 1)) << 18;   // exclusive upper bound
            plo = ((unsigned int)blo) << 18;         // inclusive lower bound
        }
        unsigned int width = phi - plo;              // >= 2^18 always
        int m = 32 - __clz(width - 1u);              // smallest m: width <= 1<<m
        g_pivot_lo = plo;
        g_pivot_hi = phi;
        g_m = m;
        g_P = 0u;
    }
}

// ---------------------------------------------------------------------------
// Full pass: provisional output + cnt_hi + candidate capture (warp-aggregated).
__global__ void __launch_bounds__(256) k_main(const float* __restrict__ x,
                                              float* __restrict__ out, int n) {
    const unsigned int plo = g_pivot_lo;
    const unsigned int phi = g_pivot_hi;
    int n4 = n >> 2;
    int T = gridDim.x * blockDim.x;
    int tid = blockIdx.x * blockDim.x + threadIdx.x;
    int lane = threadIdx.x & 31;
    int nfull = n4 - (n4 % T);   // uniform trip count -> safe full-warp ballots

    const float4* x4 = (const float4*)x;
    float4* o4 = (float4*)out;
    unsigned int cnt = 0u;

    for (int i = tid; i < nfull; i += T) {
        float4 v = x4[i];
        unsigned int a[4];
        a[0] = __float_as_uint(v.x) & 0x7FFFFFFFu;
        a[1] = __float_as_uint(v.y) & 0x7FFFFFFFu;
        a[2] = __float_as_uint(v.z) & 0x7FFFFFFFu;
        a[3] = __float_as_uint(v.w) & 0x7FFFFFFFu;
        cnt += (a[0] >= phi) + (a[1] >= phi) + (a[2] >= phi) + (a[3] >= phi);
        float4 o;
        o.x = (a[0] >= plo) ? v.x : 0.0f;
        o.y = (a[1] >= plo) ? v.y : 0.0f;
        o.z = (a[2] >= plo) ? v.z : 0.0f;
        o.w = (a[3] >= plo) ? v.w : 0.0f;
        o4[i] = o;   // candidates get provisional x; fixup zeroes losers later

#pragma unroll
        for (int c = 0; c < 4; c++) {
            bool pred = (a[c] >= plo) && (a[c] < phi);
            unsigned int mask = __ballot_sync(0xFFFFFFFFu, pred);
            if (mask) {
                unsigned int cm = __popc(mask);
                int leader = __ffs(mask) - 1;
                unsigned int base = 0u;
                if (lane == leader) base = atomicAdd(&g_ncand, cm);
                base = __shfl_sync(0xFFFFFFFFu, base, leader);
                if (pred) {
                    unsigned int pos = base + __popc(mask & ((1u << lane) - 1u));
                    if (pos < CAND_CAP) {
                        g_cand_v[pos] = a[c];
                        g_cand_idx[pos] = (unsigned int)(4 * i + c);
                    }
                }
            }
        }
    }

    // tail (non-uniform region): no ballots, direct atomics (tiny)
    for (int e = nfull * 4 + tid; e < n; e += T) {
        float xv = x[e];
        unsigned int a = __float_as_uint(xv) & 0x7FFFFFFFu;
        cnt += (a >= phi);
        out[e] = (a >= plo) ? xv : 0.0f;
        if (a >= plo && a < phi) {
            unsigned int pos = atomicAdd(&g_ncand, 1u);
            if (pos < CAND_CAP) { g_cand_v[pos] = a; g_cand_idx[pos] = (unsigned int)e; }
        }
    }

    cnt = __reduce_add_sync(0xFFFFFFFFu, cnt);
    if (lane == 0 && cnt) atomicAdd(&g_cnt_hi, cnt);
}

// ---------------------------------------------------------------------------
// Radix-select round over candidates: histogram of the next <=11 bits.
__global__ void k_rhist() {
    if (g_done) return;
    unsigned int n = g_ncand; if (n > CAND_CAP) n = CAND_CAP;
    const unsigned int plo = g_pivot_lo;
    const int m = g_m;
    const unsigned int P = g_P;
    const int s = (m > 11) ? (m - 11) : 0;
    unsigned int T = gridDim.x * blockDim.x;
    for (unsigned int i = blockIdx.x * blockDim.x + threadIdx.x; i < n; i += T) {
        unsigned int v = g_cand_v[i] - plo;
        if ((v >> m) == P) {
            unsigned int bin = (v >> s) & ((1u << (m - s)) - 1u);
            atomicAdd(&g_hist2[bin], 1u);
        }
    }
}

// Pick the bin containing the remaining rank (descending), update state.
__global__ void k_rscan(long long k) {
    if (g_done) return;
    __shared__ unsigned int cs[1024];
    int t = threadIdx.x;
    const int m = g_m;
    const unsigned int P = g_P;
    const int s = (m > 11) ? (m - 11) : 0;
    const int nb = 1 << (m - s);

    int p0 = 2 * t, p1 = 2 * t + 1;  // descending positions
    unsigned int c0 = (p0 < nb) ? g_hist2[nb - 1 - p0] : 0u;
    unsigned int c1 = (p1 < nb) ? g_hist2[nb - 1 - p1] : 0u;
    unsigned int ss = c0 + c1;
    cs[t] = ss;
    __syncthreads();
    for (int off = 1; off < 1024; off <<= 1) {
        unsigned int add = (t >= off) ? cs[t - off] : 0u;
        __syncthreads();
        cs[t] += add;
        __syncthreads();
    }
    unsigned int incl = cs[t];
    unsigned int excl = incl - ss;
    unsigned int total = cs[1023];

    unsigned int rr;
    if (g_round == 0) {
        long long rl = k - (long long)g_cnt_hi;
        if (rl < 1) rl = 1;
        rr = (unsigned int)rl;
    } else {
        rr = g_rr;
    }

    if (total == 0u) {
        if (t == 0) { g_thr = g_pivot_lo; g_done = 1; }
    } else {
        if (rr > total) rr = total;   // safety clamp (never triggers in practice)
        if (excl < rr && rr <= incl) {
            int psel; unsigned int nr;
            if (rr <= excl + c0) { psel = p0; nr = rr - excl; }
            else                 { psel = p1; nr = rr - excl - c0; }
            int bin = nb - 1 - psel;
            unsigned int newP = (P << (m - s)) | (unsigned int)bin;
            g_P = newP; g_m = s; g_rr = nr; g_round = g_round + 1;
            if (s == 0) { g_thr = g_pivot_lo + newP; g_done = 1; }
        }
    }
    __syncthreads();
    if (p0 < nb) g_hist2[nb - 1 - p0] = 0u;   // leave hist zeroed for next round
    if (p1 < nb) g_hist2[nb - 1 - p1] = 0u;
}

// ---------------------------------------------------------------------------
// Zero the candidates below the exact threshold (the rest already hold x).
__global__ void k_fix(float* __restrict__ out) {
    unsigned int n = g_ncand; if (n > CAND_CAP) n = CAND_CAP;
    const unsigned int thr = g_thr;
    unsigned int T = gridDim.x * blockDim.x;
    for (unsigned int i = blockIdx.x * blockDim.x + threadIdx.x; i < n; i += T) {
        if (g_cand_v[i] < thr) out[g_cand_idx[i]] = 0.0f;
    }
}

// ---------------------------------------------------------------------------
extern "C" void kernel_launch(void* const* d_in, const int* in_sizes, int n_in,
                              void* d_out, int out_size) {
    const float* x = (const float*)d_in[0];
    float* out = (float*)d_out;
    int n = in_sizes[0];

    // Bit-exact replication of python: k = max(1, int(n * (1.0/math.e)))
    long long k = (long long)((double)n * (1.0 / 2.718281828459045));
    if (k < 1) k = 1;

    int nsamp = n >> 6;

    k_reset<<<1, 1024>>>();
    if (nsamp > 0) k_sample<<<(nsamp + 255) / 256, 256>>>(x, nsamp);
    k_scan1<<<1, 1024>>>(k, nsamp);
    k_main<<<2048, 256>>>(x, out, n);
    // 3 rounds of <=11 bits each resolve up to 33 bits (max needed: 31).
    for (int r = 0; r < 3; r++) {
        k_rhist<<<512, 256>>>();
        k_rscan<<<1, 1024>>>(k);
    }
    k_fix<<<512, 256>>>(out);
}

// round 3
// speedup vs baseline: 6.5442x; 6.5442x over previous
#include <cuda_runtime.h>

// ---------------------------------------------------------------------------
// BoltzmannGateSTE: out = x * (|x| >= T), T = k-th largest |x|, k = int(N/e).
// Exact radix-select on float bit patterns. Sampling picks a narrow pivot
// window; the single full-data pass writes provisional output and captures
// window candidates via per-block SMEM buffering (no per-element global
// atomics). Small radix rounds on the compacted candidates find the exact
// threshold; a fixup pass zeroes candidates below it.
// ---------------------------------------------------------------------------

#define HIST1_BINS 8192
#define HIST2_BINS 2048
#define CAND_CAP   (4u * 1024u * 1024u)
#define MAIN_BLOCKS 2048
#define MAIN_THREADS 256
#define BUF 4096          // smem candidate buffer entries per block

__device__ unsigned int g_hist1[HIST1_BINS];
__device__ unsigned int g_hist2[HIST2_BINS];
__device__ unsigned int g_cand_v[CAND_CAP];    // abs bit patterns of candidates
__device__ unsigned int g_cand_idx[CAND_CAP];  // element indices of candidates
__device__ unsigned int g_ncand;
__device__ unsigned int g_cnt_hi;              // #elements with absbits >= pivot_hi
__device__ unsigned int g_pivot_lo;
__device__ unsigned int g_pivot_hi;
__device__ unsigned int g_P;                   // resolved high bits of (v - pivot_lo)
__device__ int          g_m;                   // remaining unresolved bits
__device__ unsigned int g_rr;                  // remaining rank within current window
__device__ int          g_round;
__device__ int          g_done;
__device__ unsigned int g_thr;                 // final threshold bit pattern

// ---------------------------------------------------------------------------
__global__ void k_reset() {
    int t = threadIdx.x;
    for (int i = t; i < HIST1_BINS; i += 1024) g_hist1[i] = 0u;
    for (int i = t; i < HIST2_BINS; i += 1024) g_hist2[i] = 0u;
    if (t == 0) {
        g_ncand = 0u; g_cnt_hi = 0u;
        g_P = 0u; g_m = 0; g_rr = 0u; g_round = 0; g_done = 0; g_thr = 0u;
    }
}

// ---------------------------------------------------------------------------
// Clustered sampling: each thread reads 8 contiguous floats at offset t*512
// (values iid -> clustered samples are statistically equivalent, 8x less
// DRAM sector traffic). SMEM-privatized histogram of top-13 abs bits.
__global__ void __launch_bounds__(256) k_sample(const float* __restrict__ x,
                                                int nthreads_s) {
    __shared__ unsigned int h[HIST1_BINS];
    for (int i = threadIdx.x; i < HIST1_BINS; i += 256) h[i] = 0u;
    __syncthreads();

    int t = blockIdx.x * blockDim.x + threadIdx.x;
    if (t < nthreads_s) {
        const float4* x4 = (const float4*)(x + ((long long)t << 9));
        float4 v0 = x4[0];
        float4 v1 = x4[1];
        float vv[8] = {v0.x, v0.y, v0.z, v0.w, v1.x, v1.y, v1.z, v1.w};
#pragma unroll
        for (int j = 0; j < 8; j++) {
            unsigned int a = __float_as_uint(vv[j]) & 0x7FFFFFFFu;
            atomicAdd(&h[a >> 18], 1u);
        }
    }
    __syncthreads();
    for (int i = threadIdx.x; i < HIST1_BINS; i += 256) {
        unsigned int c = h[i];
        if (c) atomicAdd(&g_hist1[i], c);
    }
}

// ---------------------------------------------------------------------------
// Find bucket window bracketing the threshold from the sample histogram
// (descending rank scan) with margin; set pivots + radix state.
__global__ void k_scan1(long long k, int nsamp) {
    __shared__ unsigned int cs[1024];
    __shared__ int sh_bhi, sh_blo;
    int t = threadIdx.x;

    unsigned int loc[8];
    unsigned int s = 0u;
#pragma unroll
    for (int j = 0; j < 8; j++) {
        int bin = HIST1_BINS - 1 - (t * 8 + j);   // descending value order
        loc[j] = g_hist1[bin];
        s += loc[j];
    }
    cs[t] = s;
    __syncthreads();
    for (int off = 1; off < 1024; off <<= 1) {
        unsigned int add = (t >= off) ? cs[t - off] : 0u;
        __syncthreads();
        cs[t] += add;
        __syncthreads();
    }
    long long incl = (long long)cs[t];
    long long excl = incl - (long long)s;
    long long tot  = (long long)cs[1023];

    long long sk = k >> 6;                 // expected sample rank of threshold
    if (sk < 1) sk = 1;
    const long long M = 4096;              // ~12 sigma margin
    long long R1 = sk - M; if (R1 < 1) R1 = 1;
    long long R2 = sk + M; if (R2 > tot) R2 = tot;

    if (t == 0) { sh_bhi = HIST1_BINS - 1; sh_blo = 0; }
    __syncthreads();

    if (tot > 0 && excl < R1 && R1 <= incl) {
        long long acc = excl;
#pragma unroll
        for (int j = 0; j < 8; j++) {
            acc += (long long)loc[j];
            if (acc >= R1) { sh_bhi = HIST1_BINS - 1 - (t * 8 + j); break; }
        }
    }
    if (tot > 0 && excl < R2 && R2 <= incl) {
        long long acc = excl;
#pragma unroll
        for (int j = 0; j < 8; j++) {
            acc += (long long)loc[j];
            if (acc >= R2) { sh_blo = HIST1_BINS - 1 - (t * 8 + j); break; }
        }
    }
    __syncthreads();

    if (t == 0) {
        unsigned int plo, phi;
        if (nsamp < 4096 || tot == 0) {
            plo = 0u; phi = 0x80000000u;   // tiny-input fallback: full range
        } else {
            int bhi = sh_bhi + 1; if (bhi > HIST1_BINS - 1) bhi = HIST1_BINS - 1;
            int blo = sh_blo - 1; if (blo < 0) blo = 0;
            phi = ((unsigned int)(bhi + 1)) << 18;   // exclusive upper bound
            plo = ((unsigned int)blo) << 18;         // inclusive lower bound
        }
        unsigned int width = phi - plo;
        int m = 32 - __clz(width - 1u);    // smallest m with width <= 1<<m
        g_pivot_lo = plo;
        g_pivot_hi = phi;
        g_m = m;
        g_P = 0u;
    }
}

// ---------------------------------------------------------------------------
// Full pass: provisional output + cnt_hi + candidate capture.
// Candidates go into an SMEM buffer (shared atomics only); the block flushes
// to the global buffer with ONE global atomic per flush. A barrier every
// 2 grid-stride steps bounds drift: <=2048 candidates can be added between
// flush checks, and we flush whenever s_cnt > BUF-2048, so s_cnt <= BUF always.
__global__ void __launch_bounds__(MAIN_THREADS) k_main(const float* __restrict__ x,
                                                       float* __restrict__ out, int n) {
    __shared__ unsigned int s_v[BUF];
    __shared__ unsigned int s_i[BUF];
    __shared__ unsigned int s_cnt;
    __shared__ unsigned int s_base;
    __shared__ unsigned int s_hi;
    const unsigned int plo = g_pivot_lo;
    const unsigned int phi = g_pivot_hi;
    const int tid = threadIdx.x;
    if (tid == 0) { s_cnt = 0u; s_hi = 0u; }
    __syncthreads();

    const int n4 = n >> 2;
    const int T = gridDim.x * blockDim.x;
    const float4* x4 = (const float4*)x;
    float4* o4 = (float4*)out;
    unsigned int cnt = 0u;

    for (int base = blockIdx.x * blockDim.x; base < n4; base += 2 * T) {
#pragma unroll
        for (int u = 0; u < 2; u++) {
            int i = base + u * T + tid;
            if (i < n4) {
                float4 v = x4[i];
                unsigned int a0 = __float_as_uint(v.x) & 0x7FFFFFFFu;
                unsigned int a1 = __float_as_uint(v.y) & 0x7FFFFFFFu;
                unsigned int a2 = __float_as_uint(v.z) & 0x7FFFFFFFu;
                unsigned int a3 = __float_as_uint(v.w) & 0x7FFFFFFFu;
                cnt += (a0 >= phi) + (a1 >= phi) + (a2 >= phi) + (a3 >= phi);
                float4 o;
                o.x = (a0 >= plo) ? v.x : 0.0f;
                o.y = (a1 >= plo) ? v.y : 0.0f;
                o.z = (a2 >= plo) ? v.z : 0.0f;
                o.w = (a3 >= plo) ? v.w : 0.0f;
                o4[i] = o;   // candidates hold provisional x; fixup zeroes losers
                unsigned int e = (unsigned int)(4 * i);
                if (a0 >= plo && a0 < phi) { unsigned int p = atomicAdd(&s_cnt, 1u); s_v[p] = a0; s_i[p] = e; }
                if (a1 >= plo && a1 < phi) { unsigned int p = atomicAdd(&s_cnt, 1u); s_v[p] = a1; s_i[p] = e + 1u; }
                if (a2 >= plo && a2 < phi) { unsigned int p = atomicAdd(&s_cnt, 1u); s_v[p] = a2; s_i[p] = e + 2u; }
                if (a3 >= plo && a3 < phi) { unsigned int p = atomicAdd(&s_cnt, 1u); s_v[p] = a3; s_i[p] = e + 3u; }
            }
        }
        __syncthreads();
        if (s_cnt > (unsigned int)(BUF - 2048)) {   // uniform: read after barrier
            unsigned int c = s_cnt; if (c > BUF) c = BUF;
            if (tid == 0) s_base = atomicAdd(&g_ncand, c);
            __syncthreads();
            for (unsigned int j = tid; j < c; j += MAIN_THREADS) {
                unsigned int pos = s_base + j;
                if (pos < CAND_CAP) { g_cand_v[pos] = s_v[j]; g_cand_idx[pos] = s_i[j]; }
            }
            __syncthreads();
            if (tid == 0) s_cnt = 0u;
            __syncthreads();
        }
    }

    // scalar tail (n % 4 elements): block 0 only, direct global atomics (tiny)
    if (blockIdx.x == 0) {
        for (int e = (n4 << 2) + tid; e < n; e += MAIN_THREADS) {
            float xv = x[e];
            unsigned int a = __float_as_uint(xv) & 0x7FFFFFFFu;
            cnt += (a >= phi);
            out[e] = (a >= plo) ? xv : 0.0f;
            if (a >= plo && a < phi) {
                unsigned int pos = atomicAdd(&g_ncand, 1u);
                if (pos < CAND_CAP) { g_cand_v[pos] = a; g_cand_idx[pos] = (unsigned int)e; }
            }
        }
    }

    // final flush
    __syncthreads();
    {
        unsigned int c = s_cnt; if (c > BUF) c = BUF;
        if (c) {
            if (tid == 0) s_base = atomicAdd(&g_ncand, c);
            __syncthreads();
            for (unsigned int j = tid; j < c; j += MAIN_THREADS) {
                unsigned int pos = s_base + j;
                if (pos < CAND_CAP) { g_cand_v[pos] = s_v[j]; g_cand_idx[pos] = s_i[j]; }
            }
        }
    }

    // cnt_hi: warp reduce -> smem -> one RED per block
    cnt = __reduce_add_sync(0xFFFFFFFFu, cnt);
    if ((tid & 31) == 0 && cnt) atomicAdd(&s_hi, cnt);
    __syncthreads();
    if (tid == 0 && s_hi) atomicAdd(&g_cnt_hi, s_hi);
}

// ---------------------------------------------------------------------------
// Radix-select round over candidates: SMEM-privatized histogram of the next
// <=11 bits, merged to global (nonzero bins only).
__global__ void __launch_bounds__(256) k_rhist() {
    if (g_done) return;
    __shared__ unsigned int h[HIST2_BINS];
    const int m = g_m;
    const int s = (m > 11) ? (m - 11) : 0;
    const int nb = 1 << (m - s);
    for (int i = threadIdx.x; i < HIST2_BINS; i += 256) h[i] = 0u;  // full clear (defensive)
    __syncthreads();

    unsigned int n = g_ncand; if (n > CAND_CAP) n = CAND_CAP;
    const unsigned int plo = g_pivot_lo;
    const unsigned int P = g_P;
    unsigned int T = gridDim.x * blockDim.x;
    for (unsigned int i = blockIdx.x * blockDim.x + threadIdx.x; i < n; i += T) {
        unsigned int v = g_cand_v[i] - plo;
        if ((v >> m) == P) atomicAdd(&h[(v >> s) & (unsigned int)(nb - 1)], 1u);
    }
    __syncthreads();
    for (int i = threadIdx.x; i < nb; i += 256) {
        unsigned int c = h[i];
        if (c) atomicAdd(&g_hist2[i], c);
    }
}

// Pick the bin containing the remaining rank (descending), update state.
__global__ void k_rscan(long long k) {
    if (g_done) return;
    __shared__ unsigned int cs[1024];
    int t = threadIdx.x;
    const int m = g_m;
    const unsigned int P = g_P;
    const int s = (m > 11) ? (m - 11) : 0;
    const int nb = 1 << (m - s);

    int p0 = 2 * t, p1 = 2 * t + 1;  // descending positions
    unsigned int c0 = (p0 < nb) ? g_hist2[nb - 1 - p0] : 0u;
    unsigned int c1 = (p1 < nb) ? g_hist2[nb - 1 - p1] : 0u;
    unsigned int ss = c0 + c1;
    cs[t] = ss;
    __syncthreads();
    for (int off = 1; off < 1024; off <<= 1) {
        unsigned int add = (t >= off) ? cs[t - off] : 0u;
        __syncthreads();
        cs[t] += add;
        __syncthreads();
    }
    unsigned int incl = cs[t];
    unsigned int excl = incl - ss;
    unsigned int total = cs[1023];

    unsigned int rr;
    if (g_round == 0) {
        long long rl = k - (long long)g_cnt_hi;
        if (rl < 1) rl = 1;
        rr = (unsigned int)rl;
    } else {
        rr = g_rr;
    }

    if (total == 0u) {
        if (t == 0) { g_thr = g_pivot_lo; g_done = 1; }
    } else {
        if (rr > total) rr = total;   // safety clamp
        if (excl < rr && rr <= incl) {
            int psel; unsigned int nr;
            if (rr <= excl + c0) { psel = p0; nr = rr - excl; }
            else                 { psel = p1; nr = rr - excl - c0; }
            int bin = nb - 1 - psel;
            unsigned int newP = (P << (m - s)) | (unsigned int)bin;
            g_P = newP; g_m = s; g_rr = nr; g_round = g_round + 1;
            if (s == 0) { g_thr = g_pivot_lo + newP; g_done = 1; }
        }
    }
    __syncthreads();
    if (p0 < nb) g_hist2[nb - 1 - p0] = 0u;   // leave hist zeroed for next round
    if (p1 < nb) g_hist2[nb - 1 - p1] = 0u;
}

// ---------------------------------------------------------------------------
// Zero the candidates below the exact threshold (the rest already hold x).
__global__ void __launch_bounds__(256) k_fix(float* __restrict__ out) {
    unsigned int n = g_ncand; if (n > CAND_CAP) n = CAND_CAP;
    const unsigned int thr = g_thr;
    unsigned int T = gridDim.x * blockDim.x;
    for (unsigned int i = blockIdx.x * blockDim.x + threadIdx.x; i < n; i += T) {
        if (g_cand_v[i] < thr) out[g_cand_idx[i]] = 0.0f;
    }
}

// ---------------------------------------------------------------------------
extern "C" void kernel_launch(void* const* d_in, const int* in_sizes, int n_in,
                              void* d_out, int out_size) {
    const float* x = (const float*)d_in[0];
    float* out = (float*)d_out;
    int n = in_sizes[0];

    // Bit-exact replication of python: k = max(1, int(n * (1.0/math.e)))
    long long k = (long long)((double)n * (1.0 / 2.718281828459045));
    if (k < 1) k = 1;

    int nthreads_s = n >> 9;            // each sample thread covers 8 of 512
    int nsamp = nthreads_s << 3;        // total sampled elements (~n/64)

    k_reset<<<1, 1024>>>();
    if (nthreads_s > 0)
        k_sample<<<(nthreads_s + 255) / 256, 256>>>(x, nthreads_s);
    k_scan1<<<1, 1024>>>(k, nsamp);
    k_main<<<MAIN_BLOCKS, MAIN_THREADS>>>(x, out, n);
    // 3 rounds of <=11 bits resolve up to 33 bits (max needed: 31).
    for (int r = 0; r < 3; r++) {
        k_rhist<<<148, 256>>>();
        k_rscan<<<1, 1024>>>(k);
    }
    k_fix<<<512, 256>>>(out);
}